// round 5
// baseline (speedup 1.0000x reference)
#include <cuda_runtime.h>
#include <cuda_bf16.h>

#define N_NODES 100000
#define N_EDGES 1600000
#define IN_DIM  256
#define HIDDEN  64

// Scratch (allocation-free rule: __device__ globals)
__device__ __align__(16) float g_u[IN_DIM];   // W @ w2
__device__ float g_c;                          // b.w2 + b2
__device__ float g_deg[N_NODES];               // degree incl. self loop
__device__ float g_ss[N_NODES];                // s[v] * dinv[v]
__device__ float g_dinv[N_NODES];
__device__ float g_t[N_NODES];                 // edge-aggregated ss[src]

// K1: fused: block 0 computes u = W@w2 and c; all blocks init deg=1, t=0
__global__ void k_prep(const float* __restrict__ W, const float* __restrict__ b,
                       const float* __restrict__ w2, const float* __restrict__ b2) {
    int v = blockIdx.x * blockDim.x + threadIdx.x;
    if (v < N_NODES) { g_deg[v] = 1.0f; g_t[v] = 0.0f; }
    if (blockIdx.x == 0) {
        int i = threadIdx.x;  // 256 threads == IN_DIM
        float acc = 0.f;
#pragma unroll
        for (int h = 0; h < HIDDEN; h++) acc += W[i * HIDDEN + h] * w2[h];
        g_u[i] = acc;
        if (i == 0) {
            float cc = b2[0];
            for (int h = 0; h < HIDDEN; h++) cc += b[h] * w2[h];
            g_c = cc;
        }
    }
}

__device__ __forceinline__ void deg_bump(int d) {
    if ((unsigned)d < (unsigned)N_NODES) atomicAdd(&g_deg[d], 1.0f);
}

// K2: degree over dst row. 8 edges/thread via 2x int4 (two independent 16B loads).
__global__ void k_deg(const int* __restrict__ dst) {
    int t8 = blockIdx.x * blockDim.x + threadIdx.x;   // edges [8*t8, 8*t8+8)
    long long e = (long long)t8 * 8;
    if (e + 7 < N_EDGES) {
        int4 p0 = *(const int4*)(dst + e);
        int4 p1 = *(const int4*)(dst + e + 4);
        deg_bump(p0.x); deg_bump(p0.y); deg_bump(p0.z); deg_bump(p0.w);
        deg_bump(p1.x); deg_bump(p1.y); deg_bump(p1.z); deg_bump(p1.w);
    } else {
        for (; e < N_EDGES; e++) deg_bump(dst[e]);
    }
}

// K3: warp per node: s[v] = x[v].u ; ss = s*dinv ; dinv stored
__global__ void k_dot(const float* __restrict__ x) {
    int gtid = blockIdx.x * blockDim.x + threadIdx.x;
    int warp = gtid >> 5;
    int lane = threadIdx.x & 31;
    if (warp >= N_NODES) return;
    const float4* xp = (const float4*)(x + (size_t)warp * IN_DIM);
    const float4* up = (const float4*)g_u;
    float4 a0 = xp[lane];
    float4 a1 = xp[lane + 32];
    float4 u0 = up[lane];
    float4 u1 = up[lane + 32];
    float acc = a0.x * u0.x + a0.y * u0.y + a0.z * u0.z + a0.w * u0.w
              + a1.x * u1.x + a1.y * u1.y + a1.z * u1.z + a1.w * u1.w;
#pragma unroll
    for (int o = 16; o; o >>= 1) acc += __shfl_xor_sync(0xffffffffu, acc, o);
    if (lane == 0) {
        float di = rsqrtf(g_deg[warp]);
        g_dinv[warp] = di;
        g_ss[warp] = acc * di;
    }
}

__device__ __forceinline__ void scat1(int s, int d) {
    if ((unsigned)s < (unsigned)N_NODES && (unsigned)d < (unsigned)N_NODES)
        atomicAdd(&g_t[d], g_ss[s]);
}

// K4: scatter ss[src] into t[dst]; 8 edges/thread, int4 index loads
__global__ void k_scatter(const int* __restrict__ src,
                          const int* __restrict__ dst) {
    int t8 = blockIdx.x * blockDim.x + threadIdx.x;
    long long e = (long long)t8 * 8;
    if (e + 7 < N_EDGES) {
        int4 s0 = *(const int4*)(src + e);
        int4 s1 = *(const int4*)(src + e + 4);
        int4 d0 = *(const int4*)(dst + e);
        int4 d1 = *(const int4*)(dst + e + 4);
        scat1(s0.x, d0.x); scat1(s0.y, d0.y); scat1(s0.z, d0.z); scat1(s0.w, d0.w);
        scat1(s1.x, d1.x); scat1(s1.y, d1.y); scat1(s1.z, d1.z); scat1(s1.w, d1.w);
    } else {
        for (; e < N_EDGES; e++) scat1(src[e], dst[e]);
    }
}

// K5: out = sigmoid(dinv*(t + ss) + c)
__global__ void k_out(float* __restrict__ out) {
    int v = blockIdx.x * blockDim.x + threadIdx.x;
    if (v < N_NODES) {
        float z = g_dinv[v] * (g_t[v] + g_ss[v]) + g_c;
        out[v] = 1.0f / (1.0f + expf(-z));
    }
}

extern "C" void kernel_launch(void* const* d_in, const int* in_sizes, int n_in,
                              void* d_out, int out_size) {
    const float* x   = (const float*)d_in[0];
    const int*   ei  = (const int*)d_in[1];   // [2, N_EDGES], materialized as int32
    const float* W   = (const float*)d_in[2];
    const float* b   = (const float*)d_in[3];
    const float* w2  = (const float*)d_in[4];
    const float* b2  = (const float*)d_in[5];
    float*       out = (float*)d_out;

    const int* src = ei;
    const int* dst = ei + N_EDGES;

    int edge_threads = (N_EDGES + 7) / 8;

    k_prep<<<(N_NODES + 255) / 256, 256>>>(W, b, w2, b2);
    k_deg<<<(edge_threads + 255) / 256, 256>>>(dst);
    k_dot<<<(N_NODES * 32 + 255) / 256, 256>>>(x);
    k_scatter<<<(edge_threads + 255) / 256, 256>>>(src, dst);
    k_out<<<(N_NODES + 255) / 256, 256>>>(out);
}

// round 6
// speedup vs baseline: 1.3152x; 1.3152x over previous
#include <cuda_runtime.h>
#include <cuda_bf16.h>

#define N_NODES 100000
#define N_EDGES 1600000
#define IN_DIM  256
#define HIDDEN  64

// Scratch (allocation-free rule: __device__ globals). Module load zero-inits;
// k_out re-zeros g_deg/g_t at the end of every launch for the next replay.
__device__ __align__(16) float g_u[IN_DIM];   // W @ w2
__device__ float g_c;                          // b.w2 + b2
__device__ float g_deg[N_NODES];               // edge count (self loop added as +1 later)
__device__ float g_ss[N_NODES];                // s[v] * dinv[v]
__device__ float g_dinv[N_NODES];
__device__ float g_t[N_NODES];                 // edge-aggregated ss[src]

// K1: degree count over dst row, 4 edges/thread via int4.
//     Block 0 additionally computes u = W@w2 and c = b.w2 + b2.
__global__ void k_deg(const int* __restrict__ dst,
                      const float* __restrict__ W, const float* __restrict__ b,
                      const float* __restrict__ w2, const float* __restrict__ b2) {
    int t4 = blockIdx.x * blockDim.x + threadIdx.x;   // edges [4*t4, 4*t4+4)
    long long e = (long long)t4 * 4;
    if (e + 3 < N_EDGES) {
        int4 p = *(const int4*)(dst + e);
        if ((unsigned)p.x < (unsigned)N_NODES) atomicAdd(&g_deg[p.x], 1.0f);
        if ((unsigned)p.y < (unsigned)N_NODES) atomicAdd(&g_deg[p.y], 1.0f);
        if ((unsigned)p.z < (unsigned)N_NODES) atomicAdd(&g_deg[p.z], 1.0f);
        if ((unsigned)p.w < (unsigned)N_NODES) atomicAdd(&g_deg[p.w], 1.0f);
    } else {
        for (; e < N_EDGES; e++) {
            int d = dst[e];
            if ((unsigned)d < (unsigned)N_NODES) atomicAdd(&g_deg[d], 1.0f);
        }
    }
    if (blockIdx.x == 0) {
        int i = threadIdx.x;  // 256 threads == IN_DIM
        float acc = 0.f;
#pragma unroll
        for (int h = 0; h < HIDDEN; h++) acc += W[i * HIDDEN + h] * w2[h];
        g_u[i] = acc;
        if (i == 0) {
            float cc = b2[0];
            for (int h = 0; h < HIDDEN; h++) cc += b[h] * w2[h];
            g_c = cc;
        }
    }
}

// K2: warp per node: s[v] = x[v].u ; dinv = rsqrt(1+degcnt) ; ss = s*dinv
__global__ void k_dot(const float* __restrict__ x) {
    int gtid = blockIdx.x * blockDim.x + threadIdx.x;
    int warp = gtid >> 5;
    int lane = threadIdx.x & 31;
    if (warp >= N_NODES) return;
    const float4* xp = (const float4*)(x + (size_t)warp * IN_DIM);
    const float4* up = (const float4*)g_u;
    float4 a0 = xp[lane];
    float4 a1 = xp[lane + 32];
    float4 u0 = up[lane];
    float4 u1 = up[lane + 32];
    float acc = a0.x * u0.x + a0.y * u0.y + a0.z * u0.z + a0.w * u0.w
              + a1.x * u1.x + a1.y * u1.y + a1.z * u1.z + a1.w * u1.w;
#pragma unroll
    for (int o = 16; o; o >>= 1) acc += __shfl_xor_sync(0xffffffffu, acc, o);
    if (lane == 0) {
        float di = rsqrtf(1.0f + g_deg[warp]);   // +1 self loop
        g_dinv[warp] = di;
        g_ss[warp] = acc * di;
    }
}

// K3: scatter ss[src] into t[dst]; 4 edges/thread, int4 index loads
__global__ void k_scatter(const int* __restrict__ src,
                          const int* __restrict__ dst) {
    int t4 = blockIdx.x * blockDim.x + threadIdx.x;
    long long e = (long long)t4 * 4;
    if (e + 3 < N_EDGES) {
        int4 s = *(const int4*)(src + e);
        int4 d = *(const int4*)(dst + e);
        float v0 = ((unsigned)s.x < (unsigned)N_NODES) ? g_ss[s.x] : 0.f;
        float v1 = ((unsigned)s.y < (unsigned)N_NODES) ? g_ss[s.y] : 0.f;
        float v2 = ((unsigned)s.z < (unsigned)N_NODES) ? g_ss[s.z] : 0.f;
        float v3 = ((unsigned)s.w < (unsigned)N_NODES) ? g_ss[s.w] : 0.f;
        if ((unsigned)d.x < (unsigned)N_NODES) atomicAdd(&g_t[d.x], v0);
        if ((unsigned)d.y < (unsigned)N_NODES) atomicAdd(&g_t[d.y], v1);
        if ((unsigned)d.z < (unsigned)N_NODES) atomicAdd(&g_t[d.z], v2);
        if ((unsigned)d.w < (unsigned)N_NODES) atomicAdd(&g_t[d.w], v3);
    } else {
        for (; e < N_EDGES; e++) {
            int s = src[e], d = dst[e];
            if ((unsigned)s < (unsigned)N_NODES && (unsigned)d < (unsigned)N_NODES)
                atomicAdd(&g_t[d], g_ss[s]);
        }
    }
}

// K4: out = sigmoid(dinv*(t + ss) + c); reset g_deg/g_t for next replay
__global__ void k_out(float* __restrict__ out) {
    int v = blockIdx.x * blockDim.x + threadIdx.x;
    if (v < N_NODES) {
        float z = g_dinv[v] * (g_t[v] + g_ss[v]) + g_c;
        out[v] = 1.0f / (1.0f + expf(-z));
        g_deg[v] = 0.0f;
        g_t[v] = 0.0f;
    }
}

extern "C" void kernel_launch(void* const* d_in, const int* in_sizes, int n_in,
                              void* d_out, int out_size) {
    const float* x   = (const float*)d_in[0];
    const int*   ei  = (const int*)d_in[1];   // [2, N_EDGES], materialized as int32
    const float* W   = (const float*)d_in[2];
    const float* b   = (const float*)d_in[3];
    const float* w2  = (const float*)d_in[4];
    const float* b2  = (const float*)d_in[5];
    float*       out = (float*)d_out;

    const int* src = ei;
    const int* dst = ei + N_EDGES;

    int edge_threads = (N_EDGES + 3) / 4;   // 400000

    k_deg<<<(edge_threads + 255) / 256, 256>>>(dst, W, b, w2, b2);
    k_dot<<<(N_NODES * 32 + 255) / 256, 256>>>(x);
    k_scatter<<<(edge_threads + 255) / 256, 256>>>(src, dst);
    k_out<<<(N_NODES + 255) / 256, 256>>>(out);
}